// round 14
// baseline (speedup 1.0000x reference)
#include <cuda_runtime.h>
#include <cuda_bf16.h>
#include <cstdint>
#include <math_constants.h>

// Problem constants
#define T_STEPS 128
#define IN_SZ   64
#define H       2048
#define OUT_SZ  4096
#define G4      (4*H)

// Persistent kernel config
#define NBLK_W 128
#define GRID   NBLK_W
#define NTHR 512                 // 16 warps, K-split 2
#define COLS_PER_BLK 16
#define SMEM_COLS 12             // Whh0 columns pinned in smem (bf16)
#define SMEM_W_BYTES (SMEM_COLS * 4 * H * 2)        // 192 KB
#define SMEM_BYTES   (SMEM_W_BYTES + H * 4)         // + 8 KB h broadcast stage

// ---------------- device scratch ----------------
__device__ __align__(16) __nv_bfloat16 g_Whh0b[G4 * H];
__device__ __align__(16) uint8_t g_Wih1q[G4 * H];
__device__ __align__(16) uint8_t g_Whh1q[G4 * H];
__device__ __align__(16) float g_si1[G4], g_sh1[G4];
__device__ __align__(16) __nv_bfloat16 g_Wlb[OUT_SZ * H];
__device__ __align__(16) float g_A0[T_STEPS * G4];
__device__ __align__(16) float g_wcol0[G4];
__device__ __align__(16) float g_bsum1[G4];
__device__ __align__(16) float g_gum[T_STEPS * OUT_SZ];
__device__ uint32_t g_keys2[2 * T_STEPS];
__device__ __align__(16) float g_h0[2][H];
__device__ __align__(16) float g_h1[2][H];
__device__ __align__(16) float g_c0[H];
__device__ __align__(16) float g_c1[H];
__device__ float g_bm[NBLK_W], g_blm[NBLK_W], g_bs[NBLK_W];
__device__ int   g_bi[NBLK_W];
__device__ unsigned g_cnt;       // monotone barrier counter
__device__ unsigned g_scnt;      // monotone logit-partials counter

// ---------------- threefry2x32 (JAX partitionable) ----------------
__device__ __forceinline__ void tf2x32(uint32_t k0, uint32_t k1, uint32_t& x0, uint32_t& x1) {
    uint32_t ks2 = k0 ^ k1 ^ 0x1BD11BDAu;
    x0 += k0; x1 += k1;
#define TF_RND(r) { x0 += x1; x1 = (x1 << (r)) | (x1 >> (32 - (r))); x1 ^= x0; }
    TF_RND(13) TF_RND(15) TF_RND(26) TF_RND(6)   x0 += k1;  x1 += ks2 + 1u;
    TF_RND(17) TF_RND(29) TF_RND(16) TF_RND(24)  x0 += ks2; x1 += k0 + 2u;
    TF_RND(13) TF_RND(15) TF_RND(26) TF_RND(6)   x0 += k0;  x1 += k1 + 3u;
    TF_RND(17) TF_RND(29) TF_RND(16) TF_RND(24)  x0 += k1;  x1 += ks2 + 4u;
    TF_RND(13) TF_RND(15) TF_RND(26) TF_RND(6)   x0 += ks2; x1 += k0 + 5u;
#undef TF_RND
}

// Launch 1: bf16 conversions, keys, A0 GEMM, state init
__global__ void k_pre1(const float* __restrict__ Whh0, const float* __restrict__ Wl,
                       const float* __restrict__ Wih0, const float* __restrict__ inp,
                       const float* __restrict__ bih0, const float* __restrict__ bhh0,
                       const float* __restrict__ bih1, const float* __restrict__ bhh1,
                       const float* __restrict__ h0in, const float* __restrict__ c0in) {
    long i = (long)blockIdx.x * blockDim.x + threadIdx.x;
    if (i < (long)G4 * H) g_Whh0b[i] = __float2bfloat16(Whh0[i]);
    if (i < (long)OUT_SZ * H) g_Wlb[i] = __float2bfloat16(Wl[i]);
    if (i < G4) {
        g_wcol0[i] = Wih0[i * (IN_SZ + 1)];
        g_bsum1[i] = bih1[i] + bhh1[i];
    }
    if (i < T_STEPS) {
        uint32_t x0 = 0u, x1 = (uint32_t)i;
        tf2x32(0u, 42u, x0, x1);
        g_keys2[2 * i] = x0;
        g_keys2[2 * i + 1] = x1;
    }
    if (i < (long)T_STEPS * G4) {
        int r = (int)(i & (G4 - 1));
        int t = (int)(i >> 13);
        float acc = bih0[r] + bhh0[r];
        const float* w = Wih0 + (size_t)r * (IN_SZ + 1) + 1;
        const float* x = inp + (size_t)t * IN_SZ;
#pragma unroll
        for (int k = 0; k < IN_SZ; k++) acc += w[k] * x[k];
        g_A0[i] = acc;
    }
    if (i < H) {
        g_h0[0][i] = h0in[i];
        g_c0[i]    = c0in[i];
        g_h1[0][i] = h0in[H + i];
        g_c1[i]    = c0in[H + i];
    }
    if (i == 0) { g_cnt = 0u; g_scnt = 0u; }
}

// Launch 2: int8 quantization of both layer-1 matrices
__global__ void k_quant2(const float* __restrict__ Wih1, const float* __restrict__ Whh1) {
    int gw = (blockIdx.x * blockDim.x + threadIdx.x) >> 5;
    int lane = threadIdx.x & 31;
    if (gw >= 2 * G4) return;
    int row = (gw < G4) ? gw : gw - G4;
    const float* W = (gw < G4) ? Wih1 : Whh1;
    uint8_t* Q = (gw < G4) ? g_Wih1q : g_Whh1q;
    float* S = (gw < G4) ? g_si1 : g_sh1;
    const float4* src = (const float4*)(W + (size_t)row * H);
    float amax = 0.f;
#pragma unroll
    for (int i = 0; i < 16; i++) {
        float4 v = src[i * 32 + lane];
        amax = fmaxf(amax, fmaxf(fmaxf(fabsf(v.x), fabsf(v.y)),
                                 fmaxf(fabsf(v.z), fabsf(v.w))));
    }
#pragma unroll
    for (int o = 16; o; o >>= 1) amax = fmaxf(amax, __shfl_xor_sync(0xffffffffu, amax, o));
    float s = (amax > 0.f) ? amax * (1.0f / 127.0f) : 1.0f;
    float rs = 1.0f / s;
    if (lane == 0) S[row] = s;
    uint32_t* dst = (uint32_t*)(Q + (size_t)row * H);
#pragma unroll
    for (int i = 0; i < 16; i++) {
        float4 v = src[i * 32 + lane];
        int a = max(-127, min(127, __float2int_rn(v.x * rs))) + 128;
        int b = max(-127, min(127, __float2int_rn(v.y * rs))) + 128;
        int c = max(-127, min(127, __float2int_rn(v.z * rs))) + 128;
        int d = max(-127, min(127, __float2int_rn(v.w * rs))) + 128;
        dst[i * 32 + lane] = (uint32_t)a | ((uint32_t)b << 8) |
                             ((uint32_t)c << 16) | ((uint32_t)d << 24);
    }
}

// Launch 3: gumbel noise
__global__ void k_gumbel() {
    int idx = blockIdx.x * blockDim.x + threadIdx.x;
    int t = idx >> 12;
    int i = idx & (OUT_SZ - 1);
    uint32_t x0 = 0u, x1 = (uint32_t)i;
    tf2x32(g_keys2[2 * t], g_keys2[2 * t + 1], x0, x1);
    uint32_t bits = x0 ^ x1;
    float f = __uint_as_float((bits >> 9) | 0x3f800000u) - 1.0f;
    const float TINY = 1.17549435e-38f;
    float u = fmaxf(f + TINY, TINY);
    g_gum[idx] = -logf(-logf(u));
}

__device__ __forceinline__ float sigf(float x) { return 1.0f / (1.0f + expf(-x)); }

// ---------------- packed f32x2 primitives ----------------
typedef unsigned long long u64;

__device__ __forceinline__ u64 pack2(uint32_t lo, uint32_t hi) {
    u64 p;
    asm("mov.b64 %0, {%1, %2};" : "=l"(p) : "r"(lo), "r"(hi));
    return p;
}
__device__ __forceinline__ u64 bf2pair(uint32_t u) {
    return pack2(u << 16, u & 0xffff0000u);
}
__device__ __forceinline__ void fma2(u64& acc, u64 a, u64 b) {
    asm("fma.rn.f32x2 %0, %1, %2, %0;" : "+l"(acc) : "l"(a), "l"(b));
}
__device__ __forceinline__ u64 q2pair(uint32_t u, int k2) {
    uint32_t lo = __byte_perm(u, 0x4B000000u, 0x7650 + k2);
    uint32_t hi = __byte_perm(u, 0x4B000000u, 0x7651 + k2);
    u64 p = pack2(lo, hi);
    asm("add.rn.f32x2 %0, %0, %1;" : "+l"(p) : "l"(0xCB000080CB000080ULL));
    return p;
}
__device__ __forceinline__ float unpack_sum(u64 p) {
    uint32_t lo, hi;
    asm("mov.b64 {%0, %1}, %2;" : "=r"(lo), "=r"(hi) : "l"(p));
    return __uint_as_float(lo) + __uint_as_float(hi);
}

__device__ __forceinline__ float bfrow_h(const uint4* __restrict__ W,
                                         const u64 (&hp)[16], int lane) {
    u64 acc = 0;
#pragma unroll
    for (int i = 0; i < 4; i++) {
        uint4 w = W[i * 32 + lane];
        fma2(acc, bf2pair(w.x), hp[4 * i]);
        fma2(acc, bf2pair(w.y), hp[4 * i + 1]);
        fma2(acc, bf2pair(w.z), hp[4 * i + 2]);
        fma2(acc, bf2pair(w.w), hp[4 * i + 3]);
    }
    return unpack_sum(acc);
}
__device__ __forceinline__ float qrow_h(const uint2* __restrict__ W,
                                        const u64 (&hp)[16], int lane) {
    u64 acc = 0;
#pragma unroll
    for (int i = 0; i < 4; i++) {
        uint2 w = W[i * 32 + lane];
        fma2(acc, q2pair(w.x, 0), hp[4 * i]);
        fma2(acc, q2pair(w.x, 2), hp[4 * i + 1]);
        fma2(acc, q2pair(w.y, 0), hp[4 * i + 2]);
        fma2(acc, q2pair(w.y, 2), hp[4 * i + 3]);
    }
    return unpack_sum(acc);
}

__device__ __forceinline__ float warp_sum(float v) {
#pragma unroll
    for (int o = 16; o; o >>= 1) v += __shfl_down_sync(0xffffffffu, v, o);
    return v;
}

// monotone grid barrier (R13-proven)
__device__ __forceinline__ void gbar(unsigned target) {
    __syncthreads();
    if (threadIdx.x == 0) {
        atomicAdd(&g_cnt, 1u);
        while (*(volatile unsigned*)&g_cnt < target) {}
    }
    __syncthreads();
}

__global__ void __launch_bounds__(NTHR, 1) k_persist(const float* __restrict__ bl,
                                                     float* __restrict__ out) {
    extern __shared__ char smem[];
    const int tid  = threadIdx.x;
    const int warp = tid >> 5, lane = tid & 31;
    const int b = blockIdx.x;

    __shared__ float sgp[64][2];   // layer0 dots (for step t, written phase1 of t-1)
    __shared__ float sgi[64][2];   // Wih1 dots (for step t, written phase1 of t)
    __shared__ float sg2p[64][2];  // Whh1 dots (for step t, written phase2 of t-1)
    __shared__ float slogp[32][2];
    __shared__ float sA0[64];
    __shared__ float sgum[32], sbl[32], slog[32];
    __shared__ float ssi1[64], ssh1[64];
    __shared__ float rm[4], rlm[4], rs[4], s_Mv, s_Sv, s_prev;
    __shared__ int rix[4], s_Iv;

    __nv_bfloat16* ws = (__nv_bfloat16*)smem;            // 48 Whh0 rows x 2048 bf16
    float* hs = (float*)(smem + SMEM_W_BYTES);           // 8 KB h broadcast stage
    const int c0 = b * COLS_PER_BLK;
    const int half = warp & 1;
    const int rw = warp >> 1;

    float c0r = 0.f, c1r = 0.f, w0r[4], bs1r[4];
    if (tid < COLS_PER_BLK) {
        int col = c0 + tid;
        c0r = g_c0[col];
        c1r = g_c1[col];
#pragma unroll
        for (int g = 0; g < 4; g++) {
            w0r[g]  = g_wcol0[g * H + col];
            bs1r[g] = g_bsum1[g * H + col];
        }
    }
    if (tid < 32) sbl[tid] = bl[b * 32 + tid];
    if (tid < 64) {
        int j = tid >> 2, g = tid & 3;
        int row = g * H + c0 + j;
        ssi1[tid] = g_si1[row];
        ssh1[tid] = g_sh1[row];
    }
    if (tid == 0) s_prev = 1.0f;

    // load Whh0 slice into smem (rows: slot = j*4+g, j<SMEM_COLS)
    for (int slot = warp; slot < SMEM_COLS * 4; slot += 16) {
        int j = slot >> 2, g = slot & 3;
        const uint4* src = (const uint4*)(g_Whh0b + ((size_t)(g * H + c0 + j)) * H);
        uint4* dst = (uint4*)(ws + (size_t)slot * H);
        for (int i = lane; i < H / 8; i += 32) dst[i] = src[i];
    }

    u64 hp[16];

#define STAGE_H(SRCPTR)                                                     \
    {   const float4* _s = (const float4*)(SRCPTR);                         \
        float4* _d = (float4*)hs;                                           \
        _d[tid] = __ldcg(_s + tid);  }

#define LOAD_HP()                                                           \
    {   const ulonglong2* _h = (const ulonglong2*)hs + half * 256;          \
        _Pragma("unroll")                                                   \
        for (int i = 0; i < 4; i++) {                                       \
            ulonglong2 _a = _h[(i * 32 + lane) * 2];                        \
            ulonglong2 _b = _h[(i * 32 + lane) * 2 + 1];                    \
            hp[4 * i]     = _a.x;  hp[4 * i + 1] = _a.y;                    \
            hp[4 * i + 2] = _b.x;  hp[4 * i + 3] = _b.y; } }

// 8 Whh0 half-row dots against current hp -> sgp
#define WHH0_DOTS()                                                         \
    _Pragma("unroll")                                                       \
    for (int r = 0; r < 8; r++) {                                           \
        int ri = rw + 8 * r;                                                \
        int j = ri >> 2, g = ri & 3;                                        \
        const uint4* W = ((j < SMEM_COLS)                                   \
            ? (const uint4*)(ws + (size_t)ri * H)                           \
            : (const uint4*)(g_Whh0b + ((size_t)(g * H + c0 + j)) * H)) + half * 128; \
        float acc = warp_sum(bfrow_h(W, hp, lane));                         \
        if (lane == 0) sgp[ri][half] = acc;                                 \
    }

// 8 Whh1 int8 half-row dots against current hp -> sg2p
#define WHH1_DOTS()                                                         \
    _Pragma("unroll")                                                       \
    for (int r = 0; r < 8; r++) {                                           \
        int ri = rw + 8 * r;                                                \
        int j = ri >> 2, g = ri & 3;                                        \
        const uint2* W = (const uint2*)(g_Whh1q + ((size_t)(g * H + c0 + j)) * H) + half * 128; \
        float acc = warp_sum(qrow_h(W, hp, lane));                          \
        if (lane == 0) sg2p[ri][half] = acc;                                \
    }

// replicated combine of 128 logit-partials (identical result in all blocks)
#define COMBINE(STEP_T1)                                                    \
    {   float pm = -CUDART_INF_F; int pi = 0; float lm = -CUDART_INF_F;     \
        if (tid < NBLK_W) {                                                 \
            pm = __ldcg(&g_bm[tid]);                                        \
            pi = __ldcg(&g_bi[tid]);                                        \
            lm = __ldcg(&g_blm[tid]);                                       \
        }                                                                   \
        _Pragma("unroll")                                                   \
        for (int o = 16; o; o >>= 1) {                                      \
            float om = __shfl_down_sync(0xffffffffu, pm, o);                \
            int   oi = __shfl_down_sync(0xffffffffu, pi, o);                \
            float ol = __shfl_down_sync(0xffffffffu, lm, o);                \
            if (om > pm || (om == pm && oi < pi)) { pm = om; pi = oi; }     \
            lm = fmaxf(lm, ol);                                             \
        }                                                                   \
        if (lane == 0 && warp < 4) { rm[warp] = pm; rix[warp] = pi; rlm[warp] = lm; } \
        __syncthreads();                                                    \
        if (tid == 0) {                                                     \
            pm = rm[0]; pi = rix[0]; lm = rlm[0];                           \
            _Pragma("unroll")                                               \
            for (int w = 1; w < 4; w++) {                                   \
                if (rm[w] > pm || (rm[w] == pm && rix[w] < pi)) { pm = rm[w]; pi = rix[w]; } \
                lm = fmaxf(lm, rlm[w]);                                     \
            }                                                               \
            s_Mv = lm; s_Iv = pi; s_prev = (float)pi;                       \
            if (b == 0) out[STEP_T1] = (float)pi;                           \
        }                                                                   \
        __syncthreads();                                                    \
        float _M = s_Mv;                                                    \
        float contrib = 0.f;                                                \
        if (tid < NBLK_W)                                                   \
            contrib = __ldcg(&g_bs[tid]) * expf(__ldcg(&g_blm[tid]) - _M);  \
        contrib = warp_sum(contrib);                                        \
        if (lane == 0 && warp < 4) rs[warp] = contrib;                      \
        __syncthreads();                                                    \
        if (tid == 0) s_Sv = rs[0] + rs[1] + rs[2] + rs[3];                 \
        __syncthreads();  }

    // ======== prologue: layer0 dots (t=0) from h0 init; Whh1 dots (t=0) from h1 init ====
    __syncthreads();
    STAGE_H(g_h0[0]);
    __syncthreads();
    LOAD_HP();
    WHH0_DOTS();
    __syncthreads();
    STAGE_H(g_h1[0]);
    __syncthreads();
    LOAD_HP();
    WHH1_DOTS();

    for (int t = 0; t < T_STEPS; t++) {
        int ph = t & 1;

        __syncthreads();   // protects hs/sgp/sg2p/slog reuse
        // prefetch A0/gumbel slices (streaming)
        if (tid < 64) sA0[tid] = __ldcs(&g_A0[t * G4 + (tid & 3) * H + c0 + (tid >> 2)]);
        else if (tid < 96) sgum[tid - 64] = __ldcs(&g_gum[t * OUT_SZ + b * 32 + (tid - 64)]);

        // ======== sampler wait + replicated combine (step t-1) ========
        if (tid == 0 && t > 0) {
            while (*(volatile unsigned*)&g_scnt < (unsigned)(NBLK_W * t)) {}
        }
        __syncthreads();
        if (t > 0) {
            COMBINE(t - 1);
            if (tid >= 32 && tid < 64) {
                __stcs(&out[T_STEPS + (size_t)(t - 1) * OUT_SZ + b * 32 + (tid - 32)],
                       expf(slog[tid - 32] - s_Mv) / s_Sv);
            }
        }

        // ======== cell0: uses sgp (layer0 dots, computed last iteration) ========
        if (tid < COLS_PER_BLK) {
            int col = c0 + tid;
            float prev = s_prev;
            float gg[4];
#pragma unroll
            for (int g = 0; g < 4; g++) {
                int ri = tid * 4 + g;
                gg[g] = sgp[ri][0] + sgp[ri][1] + sA0[ri] + w0r[g] * prev;
            }
            c0r = sigf(gg[1]) * c0r + sigf(gg[0]) * tanhf(gg[2]);
            __stcg(&g_h0[ph ^ 1][col], sigf(gg[3]) * tanhf(c0r));
            __threadfence();
        }
        gbar((unsigned)(2 * t + 1) * NBLK_W);

        // ======== FUSED PHASE 1: h0_new -> {Wih1 dots (t), Whh0 dots (t+1)} ========
        STAGE_H(g_h0[ph ^ 1]);
        __syncthreads();
        LOAD_HP();
#pragma unroll
        for (int r = 0; r < 8; r++) {
            int ri = rw + 8 * r;
            int j = ri >> 2, g = ri & 3;
            const uint2* W = (const uint2*)(g_Wih1q + ((size_t)(g * H + c0 + j)) * H)
                             + half * 128;
            float acc = warp_sum(qrow_h(W, hp, lane));
            if (lane == 0) sgi[ri][half] = acc;
        }
        WHH0_DOTS();   // layer0 dots for step t+1 (same hp!)
        __syncthreads();

        // ======== cell1: Wih1 dots (sgi) + Whh1 dots (sg2p, from last iteration) ====
        if (tid < COLS_PER_BLK) {
            int col = c0 + tid;
            float gg[4];
#pragma unroll
            for (int g = 0; g < 4; g++) {
                int ri = tid * 4 + g;
                gg[g] = (sgi[ri][0] + sgi[ri][1]) * ssi1[ri]
                      + (sg2p[ri][0] + sg2p[ri][1]) * ssh1[ri] + bs1r[g];
            }
            c1r = sigf(gg[1]) * c1r + sigf(gg[0]) * tanhf(gg[2]);
            __stcg(&g_h1[ph ^ 1][col], sigf(gg[3]) * tanhf(c1r));
            __threadfence();
        }
        gbar((unsigned)(2 * t + 2) * NBLK_W);

        // ======== FUSED PHASE 2: h1_new -> {Wl dots + publish, then Whh1 dots (t+1)} ====
        STAGE_H(g_h1[ph ^ 1]);
        __syncthreads();
        LOAD_HP();
#pragma unroll
        for (int r = 0; r < 4; r++) {
            int s = rw + 8 * r;
            int row = b * 32 + s;
            const uint4* W = (const uint4*)(g_Wlb + (size_t)row * H) + half * 128;
            float acc = warp_sum(bfrow_h(W, hp, lane));
            if (lane == 0) slogp[s][half] = acc;
        }
        __syncthreads();
        if (warp == 0) {   // publish partials IMMEDIATELY (Whh1 dots trail behind)
            float lg = slogp[lane][0] + slogp[lane][1] + sbl[lane];
            slog[lane] = lg;
            float pp = lg + sgum[lane];
            int idx = b * 32 + lane;
            float bm = pp; int bi = idx; float lm = lg;
#pragma unroll
            for (int o = 16; o; o >>= 1) {
                float om = __shfl_down_sync(0xffffffffu, bm, o);
                int   oi = __shfl_down_sync(0xffffffffu, bi, o);
                float ol = __shfl_down_sync(0xffffffffu, lm, o);
                if (om > bm || (om == bm && oi < bi)) { bm = om; bi = oi; }
                lm = fmaxf(lm, ol);
            }
            lm = __shfl_sync(0xffffffffu, lm, 0);
            float e = expf(lg - lm);
            e = warp_sum(e);
            if (lane == 0) {
                __stcg(&g_bm[b], bm);
                __stcg(&g_bi[b], bi);
                __stcg(&g_blm[b], lm);
                __stcg(&g_bs[b], e);
                __threadfence();
                atomicAdd(&g_scnt, 1u);
            }
        }
        WHH1_DOTS();   // Whh1 dots for step t+1 (same hp!); hidden under sampler wait
    }

    // ======== epilogue: combine step T-1, write out[T-1] + probs(T-1) ========
    if (tid == 0) {
        while (*(volatile unsigned*)&g_scnt < (unsigned)(NBLK_W * T_STEPS)) {}
    }
    __syncthreads();
    COMBINE(T_STEPS - 1);
    if (tid < 32) {
        __stcs(&out[T_STEPS + (size_t)(T_STEPS - 1) * OUT_SZ + b * 32 + tid],
               expf(slog[tid] - s_Mv) / s_Sv);
    }
}

// ---------------- host launcher ----------------
extern "C" void kernel_launch(void* const* d_in, const int* in_sizes, int n_in,
                              void* d_out, int out_size) {
    const float* input = (const float*)d_in[0];
    const float* h0    = (const float*)d_in[1];
    const float* c0    = (const float*)d_in[2];
    const float* Wih0  = (const float*)d_in[3];
    const float* Whh0  = (const float*)d_in[4];
    const float* bih0  = (const float*)d_in[5];
    const float* bhh0  = (const float*)d_in[6];
    const float* Wih1  = (const float*)d_in[7];
    const float* Whh1  = (const float*)d_in[8];
    const float* bih1  = (const float*)d_in[9];
    const float* bhh1  = (const float*)d_in[10];
    const float* Wl    = (const float*)d_in[11];
    const float* bl    = (const float*)d_in[12];
    float* out = (float*)d_out;

    cudaFuncSetAttribute(k_persist, cudaFuncAttributeMaxDynamicSharedMemorySize, SMEM_BYTES);

    k_pre1<<<(G4 * H + 255) / 256, 256>>>(Whh0, Wl, Wih0, input, bih0, bhh0,
                                          bih1, bhh1, h0, c0);
    k_quant2<<<(2 * G4 * 32 + 255) / 256, 256>>>(Wih1, Whh1);
    k_gumbel<<<(T_STEPS * OUT_SZ) / 256, 256>>>();
    k_persist<<<GRID, NTHR, SMEM_BYTES>>>(bl, out);
}

// round 16
// speedup vs baseline: 1.0950x; 1.0950x over previous
#include <cuda_runtime.h>
#include <cuda_bf16.h>
#include <cstdint>
#include <math_constants.h>

// Problem constants
#define T_STEPS 128
#define IN_SZ   64
#define H       2048
#define OUT_SZ  4096
#define G4      (4*H)

// Persistent kernel config
#define NBLK_W 128
#define GRID   NBLK_W
#define NTHR 512                 // 16 warps, K-split 2
#define COLS_PER_BLK 16
#define SMEM_COLS 12             // Whh0 columns pinned in smem (bf16)
#define SMEM_W_BYTES (SMEM_COLS * 4 * H * 2)        // 192 KB
#define SMEM_BYTES   (SMEM_W_BYTES + H * 4)         // + 8 KB h broadcast stage

#define S_H 8190.0f              // h quant scale (s16); overflow-safe exact s32 sums

// ---------------- device scratch ----------------
__device__ __align__(16) __nv_bfloat16 g_Whh0b[G4 * H];   // bf16 (layer0: precision-critical)
__device__ __align__(16) int8_t g_Wih1q[G4 * H];          // signed int8
__device__ __align__(16) int8_t g_Whh1q[G4 * H];          // signed int8
__device__ __align__(16) float g_si1[G4], g_sh1[G4];      // s_w / S_H combined factors
__device__ __align__(16) __nv_bfloat16 g_Wlb[OUT_SZ * H];
__device__ __align__(16) float g_A0[T_STEPS * G4];
__device__ __align__(16) float g_wcol0[G4];
__device__ __align__(16) float g_bsum1[G4];
__device__ __align__(16) float g_gum[T_STEPS * OUT_SZ];
__device__ uint32_t g_keys2[2 * T_STEPS];
__device__ __align__(16) float g_h0[2][H];
__device__ __align__(16) float g_h1[2][H];
__device__ __align__(16) float g_c0[H];
__device__ __align__(16) float g_c1[H];
__device__ float g_bm[NBLK_W], g_blm[NBLK_W], g_bs[NBLK_W];
__device__ int   g_bi[NBLK_W];
__device__ unsigned g_cnt;       // monotone barrier counter
__device__ unsigned g_scnt;      // monotone logit-partials counter

// ---------------- threefry2x32 (JAX partitionable) ----------------
__device__ __forceinline__ void tf2x32(uint32_t k0, uint32_t k1, uint32_t& x0, uint32_t& x1) {
    uint32_t ks2 = k0 ^ k1 ^ 0x1BD11BDAu;
    x0 += k0; x1 += k1;
#define TF_RND(r) { x0 += x1; x1 = (x1 << (r)) | (x1 >> (32 - (r))); x1 ^= x0; }
    TF_RND(13) TF_RND(15) TF_RND(26) TF_RND(6)   x0 += k1;  x1 += ks2 + 1u;
    TF_RND(17) TF_RND(29) TF_RND(16) TF_RND(24)  x0 += ks2; x1 += k0 + 2u;
    TF_RND(13) TF_RND(15) TF_RND(26) TF_RND(6)   x0 += k0;  x1 += k1 + 3u;
    TF_RND(17) TF_RND(29) TF_RND(16) TF_RND(24)  x0 += k1;  x1 += ks2 + 4u;
    TF_RND(13) TF_RND(15) TF_RND(26) TF_RND(6)   x0 += ks2; x1 += k0 + 5u;
#undef TF_RND
}

// Launch 1: bf16 conversions, keys, A0 GEMM, state init
__global__ void k_pre1(const float* __restrict__ Whh0, const float* __restrict__ Wl,
                       const float* __restrict__ Wih0, const float* __restrict__ inp,
                       const float* __restrict__ bih0, const float* __restrict__ bhh0,
                       const float* __restrict__ bih1, const float* __restrict__ bhh1,
                       const float* __restrict__ h0in, const float* __restrict__ c0in) {
    long i = (long)blockIdx.x * blockDim.x + threadIdx.x;
    if (i < (long)G4 * H) g_Whh0b[i] = __float2bfloat16(Whh0[i]);
    if (i < (long)OUT_SZ * H) g_Wlb[i] = __float2bfloat16(Wl[i]);
    if (i < G4) {
        g_wcol0[i] = Wih0[i * (IN_SZ + 1)];
        g_bsum1[i] = bih1[i] + bhh1[i];
    }
    if (i < T_STEPS) {
        uint32_t x0 = 0u, x1 = (uint32_t)i;
        tf2x32(0u, 42u, x0, x1);
        g_keys2[2 * i] = x0;
        g_keys2[2 * i + 1] = x1;
    }
    if (i < (long)T_STEPS * G4) {
        int r = (int)(i & (G4 - 1));
        int t = (int)(i >> 13);
        float acc = bih0[r] + bhh0[r];
        const float* w = Wih0 + (size_t)r * (IN_SZ + 1) + 1;
        const float* x = inp + (size_t)t * IN_SZ;
#pragma unroll
        for (int k = 0; k < IN_SZ; k++) acc += w[k] * x[k];
        g_A0[i] = acc;
    }
    if (i < H) {
        g_h0[0][i] = h0in[i];
        g_c0[i]    = c0in[i];
        g_h1[0][i] = h0in[H + i];
        g_c1[i]    = c0in[H + i];
    }
    if (i == 0) { g_cnt = 0u; g_scnt = 0u; }
}

// Launch 2: signed int8 quantization of both layer-1 matrices (rounding == R13)
__global__ void k_quant2(const float* __restrict__ Wih1, const float* __restrict__ Whh1) {
    int gw = (blockIdx.x * blockDim.x + threadIdx.x) >> 5;
    int lane = threadIdx.x & 31;
    if (gw >= 2 * G4) return;
    int row = (gw < G4) ? gw : gw - G4;
    const float* W = (gw < G4) ? Wih1 : Whh1;
    int8_t* Q = (gw < G4) ? g_Wih1q : g_Whh1q;
    float* S = (gw < G4) ? g_si1 : g_sh1;
    const float4* src = (const float4*)(W + (size_t)row * H);
    float amax = 0.f;
#pragma unroll
    for (int i = 0; i < 16; i++) {
        float4 v = src[i * 32 + lane];
        amax = fmaxf(amax, fmaxf(fmaxf(fabsf(v.x), fabsf(v.y)),
                                 fmaxf(fabsf(v.z), fabsf(v.w))));
    }
#pragma unroll
    for (int o = 16; o; o >>= 1) amax = fmaxf(amax, __shfl_xor_sync(0xffffffffu, amax, o));
    float s = (amax > 0.f) ? amax * (1.0f / 127.0f) : 1.0f;
    float rs = 1.0f / s;
    if (lane == 0) S[row] = s * (1.0f / S_H);   // combined dequant factor
    uint32_t* dst = (uint32_t*)(Q + (size_t)row * H);
#pragma unroll
    for (int i = 0; i < 16; i++) {
        float4 v = src[i * 32 + lane];
        int a = max(-127, min(127, __float2int_rn(v.x * rs)));
        int b = max(-127, min(127, __float2int_rn(v.y * rs)));
        int c = max(-127, min(127, __float2int_rn(v.z * rs)));
        int d = max(-127, min(127, __float2int_rn(v.w * rs)));
        dst[i * 32 + lane] = (uint32_t)(a & 0xff) | ((uint32_t)(b & 0xff) << 8) |
                             ((uint32_t)(c & 0xff) << 16) | ((uint32_t)(d & 0xff) << 24);
    }
}

// Launch 3: gumbel noise
__global__ void k_gumbel() {
    int idx = blockIdx.x * blockDim.x + threadIdx.x;
    int t = idx >> 12;
    int i = idx & (OUT_SZ - 1);
    uint32_t x0 = 0u, x1 = (uint32_t)i;
    tf2x32(g_keys2[2 * t], g_keys2[2 * t + 1], x0, x1);
    uint32_t bits = x0 ^ x1;
    float f = __uint_as_float((bits >> 9) | 0x3f800000u) - 1.0f;
    const float TINY = 1.17549435e-38f;
    float u = fmaxf(f + TINY, TINY);
    g_gum[idx] = -logf(-logf(u));
}

__device__ __forceinline__ float sigf(float x) { return 1.0f / (1.0f + expf(-x)); }

// ---------------- packed f32x2 primitives (bf16 phases) ----------------
typedef unsigned long long u64;
__device__ __forceinline__ u64 pack2(uint32_t lo, uint32_t hi) {
    u64 p;
    asm("mov.b64 %0, {%1, %2};" : "=l"(p) : "r"(lo), "r"(hi));
    return p;
}
__device__ __forceinline__ u64 bf2pair(uint32_t u) {
    return pack2(u << 16, u & 0xffff0000u);
}
__device__ __forceinline__ void fma2(u64& acc, u64 a, u64 b) {
    asm("fma.rn.f32x2 %0, %1, %2, %0;" : "+l"(acc) : "l"(a), "l"(b));
}
__device__ __forceinline__ float unpack_sum(u64 p) {
    uint32_t lo, hi;
    asm("mov.b64 {%0, %1}, %2;" : "=r"(lo), "=r"(hi) : "l"(p));
    return __uint_as_float(lo) + __uint_as_float(hi);
}
__device__ __forceinline__ float bfrow_h(const uint4* __restrict__ W,
                                         const u64 (&hp)[16], int lane) {
    u64 acc = 0;
#pragma unroll
    for (int i = 0; i < 4; i++) {
        uint4 w = W[i * 32 + lane];
        fma2(acc, bf2pair(w.x), hp[4 * i]);
        fma2(acc, bf2pair(w.y), hp[4 * i + 1]);
        fma2(acc, bf2pair(w.z), hp[4 * i + 2]);
        fma2(acc, bf2pair(w.w), hp[4 * i + 3]);
    }
    return unpack_sum(acc);
}

// ---------------- DP2A integer dot engine (layer-1 phases) ----------------
// half-row (1024 int8) dot against s16-quantized h (hq[16]: 2 elems per word)
__device__ __forceinline__ int qrow16(const uint4* __restrict__ W4,
                                      const int (&hq)[16], int lane) {
    int acc = 0;
#pragma unroll
    for (int i = 0; i < 2; i++) {
        uint4 w = W4[i * 32 + lane];
        asm("dp2a.lo.s32.s32 %0, %1, %2, %0;" : "+r"(acc) : "r"(hq[8*i+0]), "r"(w.x));
        asm("dp2a.hi.s32.s32 %0, %1, %2, %0;" : "+r"(acc) : "r"(hq[8*i+1]), "r"(w.x));
        asm("dp2a.lo.s32.s32 %0, %1, %2, %0;" : "+r"(acc) : "r"(hq[8*i+2]), "r"(w.y));
        asm("dp2a.hi.s32.s32 %0, %1, %2, %0;" : "+r"(acc) : "r"(hq[8*i+3]), "r"(w.y));
        asm("dp2a.lo.s32.s32 %0, %1, %2, %0;" : "+r"(acc) : "r"(hq[8*i+4]), "r"(w.z));
        asm("dp2a.hi.s32.s32 %0, %1, %2, %0;" : "+r"(acc) : "r"(hq[8*i+5]), "r"(w.z));
        asm("dp2a.lo.s32.s32 %0, %1, %2, %0;" : "+r"(acc) : "r"(hq[8*i+6]), "r"(w.w));
        asm("dp2a.hi.s32.s32 %0, %1, %2, %0;" : "+r"(acc) : "r"(hq[8*i+7]), "r"(w.w));
    }
    return acc;
}

__device__ __forceinline__ float warp_sum(float v) {
#pragma unroll
    for (int o = 16; o; o >>= 1) v += __shfl_down_sync(0xffffffffu, v, o);
    return v;
}
__device__ __forceinline__ int warp_sum_i(int v) {
#pragma unroll
    for (int o = 16; o; o >>= 1) v += __shfl_down_sync(0xffffffffu, v, o);
    return v;
}

// monotone grid barrier (R13-proven)
__device__ __forceinline__ void gbar(unsigned target) {
    __syncthreads();
    if (threadIdx.x == 0) {
        atomicAdd(&g_cnt, 1u);
        while (*(volatile unsigned*)&g_cnt < target) {}
    }
    __syncthreads();
}

__global__ void __launch_bounds__(NTHR, 1) k_persist(const float* __restrict__ bl,
                                                     float* __restrict__ out) {
    extern __shared__ char smem[];
    const int tid  = threadIdx.x;
    const int warp = tid >> 5, lane = tid & 31;
    const int b = blockIdx.x;

    __shared__ float sgp[64][2];                 // layer0 fp partials
    __shared__ int sgq[64][2], sg2q[64][2];      // layer1 exact int partials
    __shared__ float slogp[32][2];
    __shared__ float sA0[64];
    __shared__ float sgum[32], sbl[32], slog[32];
    __shared__ float ssi1[64], ssh1[64];
    __shared__ float rm[4], rlm[4], rs[4], s_Mv, s_Sv, s_prev;
    __shared__ int rix[4], s_Iv;

    __nv_bfloat16* ws = (__nv_bfloat16*)smem;    // 48 Whh0 rows x 2048 bf16
    float* hs = (float*)(smem + SMEM_W_BYTES);   // 8 KB h broadcast stage
    const int c0 = b * COLS_PER_BLK;
    const int half = warp & 1;
    const int rw = warp >> 1;

    float c0r = 0.f, c1r = 0.f, w0r[4], bs1r[4];
    if (tid < COLS_PER_BLK) {
        int col = c0 + tid;
        c0r = g_c0[col];
        c1r = g_c1[col];
#pragma unroll
        for (int g = 0; g < 4; g++) {
            w0r[g]  = g_wcol0[g * H + col];
            bs1r[g] = g_bsum1[g * H + col];
        }
    }
    if (tid < 32) sbl[tid] = bl[b * 32 + tid];
    if (tid < 64) {
        int j = tid >> 2, g = tid & 3;
        int row = g * H + c0 + j;
        ssi1[tid] = g_si1[row];
        ssh1[tid] = g_sh1[row];
    }
    if (tid == 0) s_prev = 1.0f;

    // load Whh0 slice into smem (rows: slot = j*4+g, j<SMEM_COLS)
    for (int slot = warp; slot < SMEM_COLS * 4; slot += 16) {
        int j = slot >> 2, g = slot & 3;
        const uint4* src = (const uint4*)(g_Whh0b + ((size_t)(g * H + c0 + j)) * H);
        uint4* dst = (uint4*)(ws + (size_t)slot * H);
        for (int i = lane; i < H / 8; i += 32) dst[i] = src[i];
    }

    u64 hp[16];    // fp32 pairs (bf16 phases)
    int hq[16];    // s16 pairs (DP2A phases)

#define STAGE_H(SRCPTR)                                                     \
    {   const float4* _s = (const float4*)(SRCPTR);                         \
        float4* _d = (float4*)hs;                                           \
        _d[tid] = __ldcg(_s + tid);  }

#define LOAD_HP()                                                           \
    {   const ulonglong2* _h = (const ulonglong2*)hs + half * 256;          \
        _Pragma("unroll")                                                   \
        for (int i = 0; i < 4; i++) {                                       \
            ulonglong2 _a = _h[(i * 32 + lane) * 2];                        \
            ulonglong2 _b = _h[(i * 32 + lane) * 2 + 1];                    \
            hp[4 * i]     = _a.x;  hp[4 * i + 1] = _a.y;                    \
            hp[4 * i + 2] = _b.x;  hp[4 * i + 3] = _b.y; } }

#define LOAD_HQ()                                                           \
    {   const float4* _h4 = (const float4*)hs + half * 256;                 \
        _Pragma("unroll")                                                   \
        for (int i = 0; i < 2; i++) {                                       \
            _Pragma("unroll")                                               \
            for (int c = 0; c < 4; c++) {                                   \
                float4 v = _h4[(i * 32 + lane) * 4 + c];                    \
                int i0 = __float2int_rn(v.x * S_H);                         \
                int i1 = __float2int_rn(v.y * S_H);                         \
                int i2 = __float2int_rn(v.z * S_H);                         \
                int i3 = __float2int_rn(v.w * S_H);                         \
                int p01, p23;                                               \
                asm("cvt.pack.sat.s16.s32 %0, %1, %2;" : "=r"(p01) : "r"(i1), "r"(i0)); \
                asm("cvt.pack.sat.s16.s32 %0, %1, %2;" : "=r"(p23) : "r"(i3), "r"(i2)); \
                hq[i * 8 + c * 2] = p01; hq[i * 8 + c * 2 + 1] = p23;       \
            } } }

// replicated combine of 128 logit-partials (identical result in all blocks)
#define COMBINE(STEP_T1)                                                    \
    {   float pm = -CUDART_INF_F; int pi = 0; float lm = -CUDART_INF_F;     \
        if (tid < NBLK_W) {                                                 \
            pm = __ldcg(&g_bm[tid]);                                        \
            pi = __ldcg(&g_bi[tid]);                                        \
            lm = __ldcg(&g_blm[tid]);                                       \
        }                                                                   \
        _Pragma("unroll")                                                   \
        for (int o = 16; o; o >>= 1) {                                      \
            float om = __shfl_down_sync(0xffffffffu, pm, o);                \
            int   oi = __shfl_down_sync(0xffffffffu, pi, o);                \
            float ol = __shfl_down_sync(0xffffffffu, lm, o);                \
            if (om > pm || (om == pm && oi < pi)) { pm = om; pi = oi; }     \
            lm = fmaxf(lm, ol);                                             \
        }                                                                   \
        if (lane == 0 && warp < 4) { rm[warp] = pm; rix[warp] = pi; rlm[warp] = lm; } \
        __syncthreads();                                                    \
        if (tid == 0) {                                                     \
            pm = rm[0]; pi = rix[0]; lm = rlm[0];                           \
            _Pragma("unroll")                                               \
            for (int w = 1; w < 4; w++) {                                   \
                if (rm[w] > pm || (rm[w] == pm && rix[w] < pi)) { pm = rm[w]; pi = rix[w]; } \
                lm = fmaxf(lm, rlm[w]);                                     \
            }                                                               \
            s_Mv = lm; s_Iv = pi; s_prev = (float)pi;                       \
            if (b == 0) out[STEP_T1] = (float)pi;                           \
        }                                                                   \
        __syncthreads();                                                    \
        float _M = s_Mv;                                                    \
        float contrib = 0.f;                                                \
        if (tid < NBLK_W)                                                   \
            contrib = __ldcg(&g_bs[tid]) * expf(__ldcg(&g_blm[tid]) - _M);  \
        contrib = warp_sum(contrib);                                        \
        if (lane == 0 && warp < 4) rs[warp] = contrib;                      \
        __syncthreads();                                                    \
        if (tid == 0) s_Sv = rs[0] + rs[1] + rs[2] + rs[3];                 \
        __syncthreads();  }

    for (int t = 0; t < T_STEPS; t++) {
        int ph = t & 1;

        // ======== WINDOW A: layer0 (bf16) + Whh1 (DP2A) ========
        __syncthreads();
        STAGE_H(g_h0[ph]);
        if (tid < 64) sA0[tid] = __ldcs(&g_A0[t * G4 + (tid & 3) * H + c0 + (tid >> 2)]);
        else if (tid < 96) sgum[tid - 64] = __ldcs(&g_gum[t * OUT_SZ + b * 32 + (tid - 64)]);
        __syncthreads();
        LOAD_HP();
#pragma unroll
        for (int r = 0; r < 8; r++) {
            int ri = rw + 8 * r;
            int j = ri >> 2, g = ri & 3;
            const uint4* W = ((j < SMEM_COLS)
                ? (const uint4*)(ws + (size_t)ri * H)
                : (const uint4*)(g_Whh0b + ((size_t)(g * H + c0 + j)) * H)) + half * 128;
            float acc = warp_sum(bfrow_h(W, hp, lane));
            if (lane == 0) sgp[ri][half] = acc;
        }

        // Whh1 (int8 DP2A) @ h1_old -> sg2q partials (off critical path)
        __syncthreads();
        STAGE_H(g_h1[ph]);
        __syncthreads();
        LOAD_HQ();
#pragma unroll
        for (int r = 0; r < 8; r++) {
            int ri = rw + 8 * r;
            int j = ri >> 2, g = ri & 3;
            const uint4* W = (const uint4*)(g_Whh1q + ((size_t)(g * H + c0 + j)) * H)
                             + half * 64;
            int acc = warp_sum_i(qrow16(W, hq, lane));
            if (lane == 0) sg2q[ri][half] = acc;
        }

        // ======== sampler wait + replicated combine (step t-1) ========
        if (tid == 0 && t > 0) {
            while (*(volatile unsigned*)&g_scnt < (unsigned)(NBLK_W * t)) {}
        }
        __syncthreads();
        if (t > 0) {
            COMBINE(t - 1);
            if (tid >= 32 && tid < 64) {
                __stcs(&out[T_STEPS + (size_t)(t - 1) * OUT_SZ + b * 32 + (tid - 32)],
                       expf(slog[tid - 32] - s_Mv) / s_Sv);
            }
        }

        // ======== cell0 ========
        if (tid < COLS_PER_BLK) {
            int col = c0 + tid;
            float prev = s_prev;
            float gg[4];
#pragma unroll
            for (int g = 0; g < 4; g++) {
                int ri = tid * 4 + g;
                gg[g] = sgp[ri][0] + sgp[ri][1] + sA0[ri] + w0r[g] * prev;
            }
            c0r = sigf(gg[1]) * c0r + sigf(gg[0]) * tanhf(gg[2]);
            __stcg(&g_h0[ph ^ 1][col], sigf(gg[3]) * tanhf(c0r));
            __threadfence();
        }
        gbar((unsigned)(2 * t + 1) * NBLK_W);

        // ======== layer1 critical half: Wih1 (int8 DP2A) @ h0_new ========
        STAGE_H(g_h0[ph ^ 1]);
        __syncthreads();
        LOAD_HQ();
#pragma unroll
        for (int r = 0; r < 8; r++) {
            int ri = rw + 8 * r;
            int j = ri >> 2, g = ri & 3;
            const uint4* W = (const uint4*)(g_Wih1q + ((size_t)(g * H + c0 + j)) * H)
                             + half * 64;
            int acc = warp_sum_i(qrow16(W, hq, lane));
            if (lane == 0) sgq[ri][half] = acc;
        }
        __syncthreads();
        if (tid < COLS_PER_BLK) {
            int col = c0 + tid;
            float gg[4];
#pragma unroll
            for (int g = 0; g < 4; g++) {
                int ri = tid * 4 + g;
                gg[g] = (float)(sgq[ri][0] + sgq[ri][1]) * ssi1[ri]
                      + (float)(sg2q[ri][0] + sg2q[ri][1]) * ssh1[ri] + bs1r[g];
            }
            c1r = sigf(gg[1]) * c1r + sigf(gg[0]) * tanhf(gg[2]);
            __stcg(&g_h1[ph ^ 1][col], sigf(gg[3]) * tanhf(c1r));
            __threadfence();
        }
        gbar((unsigned)(2 * t + 2) * NBLK_W);

        // ======== logits: Wl (bf16) @ h1_new (fp32), half-rows ========
        STAGE_H(g_h1[ph ^ 1]);
        __syncthreads();
        LOAD_HP();
#pragma unroll
        for (int r = 0; r < 4; r++) {
            int s = rw + 8 * r;
            int row = b * 32 + s;
            const uint4* W = (const uint4*)(g_Wlb + (size_t)row * H) + half * 128;
            float acc = warp_sum(bfrow_h(W, hp, lane));
            if (lane == 0) slogp[s][half] = acc;
        }
        __syncthreads();

        // block-local partials + arrival (warp 0 only)
        if (warp == 0) {
            float lg = slogp[lane][0] + slogp[lane][1] + sbl[lane];
            slog[lane] = lg;
            float pp = lg + sgum[lane];
            int idx = b * 32 + lane;
            float bm = pp; int bi = idx; float lm = lg;
#pragma unroll
            for (int o = 16; o; o >>= 1) {
                float om = __shfl_down_sync(0xffffffffu, bm, o);
                int   oi = __shfl_down_sync(0xffffffffu, bi, o);
                float ol = __shfl_down_sync(0xffffffffu, lm, o);
                if (om > bm || (om == bm && oi < bi)) { bm = om; bi = oi; }
                lm = fmaxf(lm, ol);
            }
            lm = __shfl_sync(0xffffffffu, lm, 0);
            float e = expf(lg - lm);
            e = warp_sum(e);
            if (lane == 0) {
                __stcg(&g_bm[b], bm);
                __stcg(&g_bi[b], bi);
                __stcg(&g_blm[b], lm);
                __stcg(&g_bs[b], e);
                __threadfence();
                atomicAdd(&g_scnt, 1u);
            }
        }
    }

    // ======== epilogue: combine step T-1 ========
    if (tid == 0) {
        while (*(volatile unsigned*)&g_scnt < (unsigned)(NBLK_W * T_STEPS)) {}
    }
    __syncthreads();
    COMBINE(T_STEPS - 1);
    if (tid < 32) {
        __stcs(&out[T_STEPS + (size_t)(T_STEPS - 1) * OUT_SZ + b * 32 + tid],
               expf(slog[tid] - s_Mv) / s_Sv);
    }
}

// ---------------- host launcher ----------------
extern "C" void kernel_launch(void* const* d_in, const int* in_sizes, int n_in,
                              void* d_out, int out_size) {
    const float* input = (const float*)d_in[0];
    const float* h0    = (const float*)d_in[1];
    const float* c0    = (const float*)d_in[2];
    const float* Wih0  = (const float*)d_in[3];
    const float* Whh0  = (const float*)d_in[4];
    const float* bih0  = (const float*)d_in[5];
    const float* bhh0  = (const float*)d_in[6];
    const float* Wih1  = (const float*)d_in[7];
    const float* Whh1  = (const float*)d_in[8];
    const float* bih1  = (const float*)d_in[9];
    const float* bhh1  = (const float*)d_in[10];
    const float* Wl    = (const float*)d_in[11];
    const float* bl    = (const float*)d_in[12];
    float* out = (float*)d_out;

    cudaFuncSetAttribute(k_persist, cudaFuncAttributeMaxDynamicSharedMemorySize, SMEM_BYTES);

    k_pre1<<<(G4 * H + 255) / 256, 256>>>(Whh0, Wl, Wih0, input, bih0, bhh0,
                                          bih1, bhh1, h0, c0);
    k_quant2<<<(2 * G4 * 32 + 255) / 256, 256>>>(Wih1, Whh1);
    k_gumbel<<<(T_STEPS * OUT_SZ) / 256, 256>>>();
    k_persist<<<GRID, NTHR, SMEM_BYTES>>>(bl, out);
}